// round 1
// baseline (speedup 1.0000x reference)
#include <cuda_runtime.h>

// DisturbanceRegressionLoss2Heads
// out: (8, 2, 30, 256, 256) fp32; target unused; output: scalar fp32 loss.

static constexpr int YT   = 30;
static constexpr int HWC  = 256 * 256;           // 65536
static constexpr int B    = 8;
static constexpr int NPIX = B * HWC;             // 524288
static constexpr int TPB  = 256;
static constexpr int NBLK = NPIX / TPB;          // 2048

__device__ double       g_acc = 0.0;
__device__ unsigned int g_cnt = 0;

__device__ __forceinline__ float warp_sum(float v) {
#pragma unroll
    for (int o = 16; o > 0; o >>= 1) v += __shfl_xor_sync(0xffffffffu, v, o);
    return v;
}

__global__ __launch_bounds__(TPB)
void disturbance_loss_kernel(const float* __restrict__ outp,
                             float* __restrict__ res) {
    const int g  = blockIdx.x * TPB + threadIdx.x;   // pixel id
    const int b  = g >> 16;                          // g / 65536
    const int hw = g & 0xFFFF;

    const float* p0 = outp + (size_t)b * (2 * YT * HWC) + hw;   // out[:,0]
    const float* p1 = p0 + (size_t)YT * HWC;                    // out[:,1]

    // ---- load out0 time series into registers (coalesced, high MLP) ----
    float v[YT];
#pragma unroll
    for (int y = 0; y < YT; ++y) v[y] = __ldg(p0 + (size_t)y * HWC);

    // ---- argmin of diff: diff[0]=-7, diff[1]=0, diff[29]=0, rest = v[y]-v[y-1]
    // first-occurrence min == strict-less scan
    float mn = -7.0f;
    int   d  = 0;
#pragma unroll
    for (int y = 2; y < YT - 1; ++y) {               // y = 2..28
        float dv = v[y] - v[y - 1];
        if (dv < mn) { mn = dv; d = y; }
    }

    // ---- data-dependent segment sums (predicated, registers only) ----
    float Sy_b = 0.f, Sty_b = 0.f, Sy_a = 0.f, Sxy_a = 0.f;
#pragma unroll
    for (int t = 0; t < YT; ++t) {
        float tv = v[t];
        if (t < d) { Sy_b += tv; Sty_b += (float)t * tv; }
        else       { Sy_a += tv; Sxy_a += (float)(t - d) * tv; }
    }

    const float nb = (float)d;
    const float na = (float)(YT - d);                // always >= 2

    // segment "before": n may be 0 (then all sums are 0 -> slope=0, icpt=0)
    float nsb  = fmaxf(nb, 1.f);
    float mxb  = 0.5f * nb * (nb - 1.f) / nsb;       // Sx/n_safe
    float myb  = Sy_b / nsb;
    float covb = Sty_b - mxb * Sy_b;
    float varb = nb * (nb * nb - 1.f) * (1.f / 12.f);
    float slb  = (varb > 0.f) ? covb / fmaxf(varb, 1.f) : 0.f;
    float scb  = fminf(fmaxf(slb, 0.f), 2.f);
    float icb  = fminf(fmaxf(myb - slb * mxb, 0.f), 100.f);

    // segment "after": n >= 2, var > 0 always
    float mxa  = 0.5f * (na - 1.f);
    float mya  = Sy_a / na;
    float cova = Sxy_a - mxa * Sy_a;
    float vara = na * (na * na - 1.f) * (1.f / 12.f);
    float sla  = cova / fmaxf(vara, 1.f);
    float sca  = fminf(fmaxf(sla, 0.f), 2.f);
    float ica  = fminf(fmaxf(mya - sla * mxa, 0.f), 100.f);

    // ---- stream out1 once; accumulate squared error of piecewise fit ----
    float acc = 0.f;
#pragma unroll
    for (int t = 0; t < YT; ++t) {
        float y1 = __ldg(p1 + (size_t)t * HWC);
        float f  = (t < d) ? fmaf(scb, (float)t,       icb)
                           : fmaf(sca, (float)(t - d), ica);
        float r  = f - y1;
        acc = fmaf(r, r, acc);
    }

    // ---- block reduction: warp shuffle -> shared -> one double atomic ----
    float ws = warp_sum(acc);
    __shared__ float sm[TPB / 32];
    const int wid  = threadIdx.x >> 5;
    const int lane = threadIdx.x & 31;
    if (lane == 0) sm[wid] = ws;
    __syncthreads();
    if (wid == 0) {
        float s = (lane < TPB / 32) ? sm[lane] : 0.f;
#pragma unroll
        for (int o = (TPB / 32) >> 1; o > 0; o >>= 1)
            s += __shfl_xor_sync(0xffffffffu, s, o);
        if (lane == 0) {
            atomicAdd(&g_acc, (double)s);
            __threadfence();
            unsigned t = atomicInc(&g_cnt, NBLK - 1);   // wraps to 0 on last
            if (t == (unsigned)(NBLK - 1)) {
                double tot = atomicAdd(&g_acc, 0.0);    // coherent read
                *res = (float)(tot * (1.0 / ((double)YT * (double)NPIX)));
                atomicExch(reinterpret_cast<unsigned long long*>(&g_acc), 0ULL);
            }
        }
    }
}

extern "C" void kernel_launch(void* const* d_in, const int* in_sizes, int n_in,
                              void* d_out, int out_size) {
    (void)in_sizes; (void)n_in; (void)out_size;
    const float* outp = (const float*)d_in[0];      // 'out' per metadata order
    float*       res  = (float*)d_out;
    disturbance_loss_kernel<<<NBLK, TPB>>>(outp, res);
}

// round 2
// speedup vs baseline: 1.1655x; 1.1655x over previous
#include <cuda_runtime.h>

// DisturbanceRegressionLoss2Heads — single-pass prefix-capture formulation.
// out: (8, 2, 30, 256, 256) fp32; target unused; output: scalar fp32 loss.

static constexpr int YT   = 30;
static constexpr int HWC  = 256 * 256;            // 65536
static constexpr int B    = 8;
static constexpr int NPIX = B * HWC;              // 524288
static constexpr int VEC  = 4;                    // pixels per thread (float4)
static constexpr int NTHR = NPIX / VEC;           // 131072
static constexpr int TPB  = 256;
static constexpr int NBLK = NTHR / TPB;           // 512

__device__ double       g_acc = 0.0;
__device__ unsigned int g_cnt = 0;

__device__ __forceinline__ float warp_sum(float v) {
#pragma unroll
    for (int o = 16; o > 0; o >>= 1) v += __shfl_xor_sync(0xffffffffu, v, o);
    return v;
}

__global__ __launch_bounds__(TPB)
void disturbance_loss_kernel(const float* __restrict__ outp,
                             float* __restrict__ res) {
    const int g   = blockIdx.x * TPB + threadIdx.x;   // float4-group id
    const int b   = g >> 14;                          // g / (HWC/4)
    const int hw4 = g & 16383;

    const float4* p0 = reinterpret_cast<const float4*>(
                           outp + (size_t)b * (2 * YT * HWC)) + hw4;  // out[:,0]
    const float4* p1 = p0 + (size_t)YT * (HWC / 4);                   // out[:,1]

    // ---- single pass over out0: argmin with prefix-sum capture ----
    float prev[VEC], mn[VEC], py[VEC], pty[VEC], SyB[VEC], StyB[VEC];
    int   d[VEC];
#pragma unroll
    for (int l = 0; l < VEC; ++l) {
        mn[l] = -7.0f; d[l] = 0;
        py[l] = 0.f; pty[l] = 0.f; SyB[l] = 0.f; StyB[l] = 0.f;
        prev[l] = 0.f;
    }

#pragma unroll
    for (int t = 0; t < YT; ++t) {
        float4 v4 = __ldg(p0 + (size_t)t * (HWC / 4));
        float v[VEC] = {v4.x, v4.y, v4.z, v4.w};
#pragma unroll
        for (int l = 0; l < VEC; ++l) {
            if (t >= 2 && t < YT - 1) {               // y = 2..28
                float dv = v[l] - prev[l];
                if (dv < mn[l]) {                     // first-occurrence min
                    mn[l] = dv; d[l] = t;
                    SyB[l] = py[l]; StyB[l] = pty[l]; // prefix over t' < d
                }
            }
            prev[l] = v[l];
            py[l]  += v[l];
            pty[l]  = fmaf((float)t, v[l], pty[l]);
        }
    }

    // ---- per-pixel OLS coefficients (registers only) ----
    float scb[VEC], icb[VEC], sca[VEC], ica[VEC];
#pragma unroll
    for (int l = 0; l < VEC; ++l) {
        const float nb = (float)d[l];
        const float na = (float)(YT - d[l]);          // >= 2

        // before-segment (may be empty: all sums 0 -> slope 0, icpt 0)
        float nsb  = fmaxf(nb, 1.f);
        float mxb  = 0.5f * nb * (nb - 1.f) / nsb;    // Sx / n_safe
        float myb  = SyB[l] / nsb;
        float covb = StyB[l] - mxb * SyB[l];
        float varb = nb * (nb * nb - 1.f) * (1.f / 12.f);
        float slb  = (varb > 0.f) ? covb / fmaxf(varb, 1.f) : 0.f;
        scb[l]     = fminf(fmaxf(slb, 0.f), 2.f);
        icb[l]     = fminf(fmaxf(myb - slb * mxb, 0.f), 100.f);

        // after-segment via total - prefix
        float SyA  = py[l]  - SyB[l];
        float StyA = pty[l] - StyB[l];
        float SxyA = StyA - nb * SyA;                 // x = t - d
        float mxa  = 0.5f * (na - 1.f);
        float mya  = SyA / na;
        float cova = SxyA - mxa * SyA;
        float vara = na * (na * na - 1.f) * (1.f / 12.f);
        float sla  = cova / fmaxf(vara, 1.f);         // na>=2 -> var>0
        sca[l]     = fminf(fmaxf(sla, 0.f), 2.f);
        ica[l]     = fminf(fmaxf(mya - sla * mxa, 0.f), 100.f);
    }

    // ---- single pass over out1: squared error of piecewise fit ----
    float acc = 0.f;
#pragma unroll
    for (int t = 0; t < YT; ++t) {
        float4 y4 = __ldg(p1 + (size_t)t * (HWC / 4));
        float y[VEC] = {y4.x, y4.y, y4.z, y4.w};
#pragma unroll
        for (int l = 0; l < VEC; ++l) {
            float f = (t < d[l]) ? fmaf(scb[l], (float)t, icb[l])
                                 : fmaf(sca[l], (float)(t - d[l]), ica[l]);
            float r = f - y[l];
            acc = fmaf(r, r, acc);
        }
    }

    // ---- block reduction: warp shuffle -> shared -> one double atomic ----
    float ws = warp_sum(acc);
    __shared__ float sm[TPB / 32];
    const int wid  = threadIdx.x >> 5;
    const int lane = threadIdx.x & 31;
    if (lane == 0) sm[wid] = ws;
    __syncthreads();
    if (wid == 0) {
        float s = (lane < TPB / 32) ? sm[lane] : 0.f;
#pragma unroll
        for (int o = (TPB / 32) >> 1; o > 0; o >>= 1)
            s += __shfl_xor_sync(0xffffffffu, s, o);
        if (lane == 0) {
            atomicAdd(&g_acc, (double)s);
            __threadfence();
            unsigned t = atomicInc(&g_cnt, NBLK - 1);   // wraps to 0 on last
            if (t == (unsigned)(NBLK - 1)) {
                double tot = atomicAdd(&g_acc, 0.0);    // coherent read
                *res = (float)(tot * (1.0 / ((double)YT * (double)NPIX)));
                atomicExch(reinterpret_cast<unsigned long long*>(&g_acc), 0ULL);
            }
        }
    }
}

extern "C" void kernel_launch(void* const* d_in, const int* in_sizes, int n_in,
                              void* d_out, int out_size) {
    (void)in_sizes; (void)n_in; (void)out_size;
    const float* outp = (const float*)d_in[0];      // 'out' per metadata order
    float*       res  = (float*)d_out;
    disturbance_loss_kernel<<<NBLK, TPB>>>(outp, res);
}